// round 8
// baseline (speedup 1.0000x reference)
#include <cuda_runtime.h>
#include <cuda_bf16.h>
#include <cstdint>
#include <cstddef>

#define N_NODES 12288
#define IN_F    256
#define OUT_F   64
#define JSPLIT  3
#define JRANGE  (N_NODES / JSPLIT)   // 4096
#define BI      128                  // i-rows per CTA
#define TJ      64                   // k per tile
#define NTILES  (JRANGE / TJ)        // 64

// h split to bf16 hi/lo, transposed: g_bt[n][j], n in [0,128)
__device__ __nv_bfloat16 g_bt[128 * N_NODES];          // 3.1 MB
__device__ float g_part[JSPLIT][N_NODES * OUT_F];      // 9.4 MB
__device__ int   g_deg[JSPLIT][N_NODES];

// ---------------- helpers ----------------
__device__ __forceinline__ uint32_t smem_u32(const void* p) {
    uint32_t a;
    asm("{ .reg .u64 t; cvta.to.shared.u64 t, %1; cvt.u32.u64 %0, t; }"
        : "=r"(a) : "l"(p));
    return a;
}
__device__ __forceinline__ void sts64(uint32_t addr, uint32_t a, uint32_t b) {
    asm volatile("st.shared.v2.b32 [%0], {%1,%2};" :: "r"(addr), "r"(a), "r"(b) : "memory");
}
__device__ __forceinline__ void cp_async16(uint32_t dst, const void* src) {
    asm volatile("cp.async.cg.shared.global [%0], [%1], 16;" :: "r"(dst), "l"(src) : "memory");
}
__device__ __forceinline__ void ldsm4(uint32_t* r, uint32_t addr) {
    asm volatile("ldmatrix.sync.aligned.m8n8.x4.shared.b16 {%0,%1,%2,%3}, [%4];"
        : "=r"(r[0]), "=r"(r[1]), "=r"(r[2]), "=r"(r[3]) : "r"(addr));
}
__device__ __forceinline__ void mma16816(float* c, const uint32_t* a,
                                         uint32_t b0, uint32_t b1) {
    asm volatile(
        "mma.sync.aligned.m16n8k16.row.col.f32.bf16.bf16.f32 "
        "{%0,%1,%2,%3},{%4,%5,%6,%7},{%8,%9},{%0,%1,%2,%3};"
        : "+f"(c[0]), "+f"(c[1]), "+f"(c[2]), "+f"(c[3])
        : "r"(a[0]), "r"(a[1]), "r"(a[2]), "r"(a[3]), "r"(b0), "r"(b1));
}
__device__ __forceinline__ uint32_t sw128(uint32_t off) {
    return off ^ ((off >> 3) & 0x70u);
}

// ======================= Kernel 1: h = x @ W, bf16-split + transpose =======================
// smem 24.6KB -> high occupancy. x staged in two 128-col halves.
__global__ void __launch_bounds__(256)
k_gemm_h(const float* __restrict__ x, const float* __restrict__ W) {
    __shared__ float x_s[32][129];
    __shared__ float w_s[32][OUT_F];
    const int tid = threadIdx.x;
    const int ti  = tid & 31;
    const int tf  = tid >> 5;
    const int rBase = blockIdx.x * 32;

    float acc[8] = {0.f,0.f,0.f,0.f,0.f,0.f,0.f,0.f};

    #pragma unroll
    for (int xh = 0; xh < 2; xh++) {
        __syncthreads();
        // stage x cols [xh*128, xh*128+128): 1024 float4, 4 per thread
        #pragma unroll
        for (int k = 0; k < 4; k++) {
            int idx = tid + k * 256;
            int row = idx >> 5;
            int c4  = (idx & 31) << 2;
            float4 v = *reinterpret_cast<const float4*>(
                x + (size_t)(rBase + row) * IN_F + xh * 128 + c4);
            x_s[row][c4 + 0] = v.x; x_s[row][c4 + 1] = v.y;
            x_s[row][c4 + 2] = v.z; x_s[row][c4 + 3] = v.w;
        }
        for (int kc = 0; kc < 4; kc++) {
            __syncthreads();
            #pragma unroll
            for (int m = 0; m < 2; m++) {
                int idx = tid + m * 256;
                int row = idx >> 4;
                int c4  = (idx & 15) << 2;
                *reinterpret_cast<float4*>(&w_s[row][c4]) =
                    *reinterpret_cast<const float4*>(
                        W + (size_t)(xh * 128 + kc * 32 + row) * OUT_F + c4);
            }
            __syncthreads();
            #pragma unroll 8
            for (int kk = 0; kk < 32; kk++) {
                float xv = x_s[ti][kc * 32 + kk];
                float4 w0 = *reinterpret_cast<const float4*>(&w_s[kk][tf * 8]);
                float4 w1 = *reinterpret_cast<const float4*>(&w_s[kk][tf * 8 + 4]);
                acc[0] += xv * w0.x; acc[1] += xv * w0.y;
                acc[2] += xv * w0.z; acc[3] += xv * w0.w;
                acc[4] += xv * w1.x; acc[5] += xv * w1.y;
                acc[6] += xv * w1.z; acc[7] += xv * w1.w;
            }
        }
    }

    int j = rBase + ti;
    #pragma unroll
    for (int u = 0; u < 8; u++) {
        int f = tf * 8 + u;
        __nv_bfloat16 bh = __float2bfloat16(acc[u]);
        float lo = acc[u] - __bfloat162float(bh);
        __nv_bfloat16 bl = __float2bfloat16(lo);
        g_bt[(size_t)f * N_NODES + j]        = bh;
        g_bt[(size_t)(64 + f) * N_NODES + j] = bl;
    }
}

// ======================= Kernel 2: HMMA masked aggregation =======================
// partial[js][i, 0:64] = sum_{j in split} mask[i,j] * h[j,:], hi+lo combined in-register.
// CTA tile 128(i) x 128(n) x 64(k). Warps: 2M x 4N; warp owns M=64 and
// feature chunks [wn*16, wn*16+16) (hi) + [64+wn*16, ...) (lo).
// smem: A bf16 [2][128][64] @0 (32KB), B bf16 [3][128][64] @32768 (48KB)
__global__ void __launch_bounds__(256, 2)
k_aggregate(const int* __restrict__ adj) {
    extern __shared__ __align__(1024) unsigned char smem[];
    const int tid   = threadIdx.x;
    const int lane  = tid & 31;
    const int w     = tid >> 5;
    const int wm    = w & 1;          // M half (64 rows)
    const int wn    = w >> 1;         // feature chunk quarter (16 feats hi + 16 lo)
    const int iBase = blockIdx.x * BI;
    const int js    = blockIdx.y;
    const int jBeg  = js * JRANGE;

    uint32_t sbase = (smem_u32(smem) + 1023u) & ~1023u;
    const uint32_t offA = sbase;
    const uint32_t offB = sbase + 32768;

    // ---- staging geometry (single-reg swizzle bases; rows stride by k) ----
    // A: 2048 int4/tile, 8/thread: row(k)=k*16+(tid>>4), col16B=(tid&15)
    const uint32_t A_SW0 = sw128((uint32_t)((tid >> 4) * 128 + (tid & 15) * 8));
    const int4* aT = reinterpret_cast<const int4*>(
        adj + (size_t)(iBase + (tid >> 4)) * N_NODES + jBeg) + (tid & 15);
    // B: 1024 16B/tile, 4/thread: row(k)=k*32+(tid>>3), col16B=(tid&7)
    const uint32_t B_SW0 = sw128((uint32_t)((tid >> 3) * 128 + (tid & 7) * 16));
    const __nv_bfloat16* bT =
        g_bt + (size_t)(tid >> 3) * N_NODES + jBeg + (tid & 7) * 8;

    // ---- ldmatrix lane geometry ----
    const uint32_t a_ch = (uint32_t)((lane >> 4) << 4);
    const uint32_t AR0  = (uint32_t)((wm * 64 + (lane & 15)) * 128 + ((lane & 7) << 4));
    const int b_n       = (lane & 7) + ((lane >> 4) << 3);
    const uint32_t b_cb = (lane & 8) ? 16u : 0u;
    const uint32_t BR0  = (uint32_t)((wn * 16 + b_n) * 128 + ((b_n & 7) << 4));

    // ---- prologue ----
    #pragma unroll
    for (int k = 0; k < 4; k++)
        cp_async16(offB + B_SW0 + k * 4096, bT + (size_t)k * 32 * N_NODES);
    asm volatile("cp.async.commit_group;" ::: "memory");
    int4 rA[8];
    #pragma unroll
    for (int k = 0; k < 8; k++) rA[k] = __ldg(aT + (size_t)k * 16 * (N_NODES / 4));
    aT += 16;
    const __nv_bfloat16* bCur = bT + 64;

    float acc[2][4][2][4];   // [hi/lo][m-frag][n-frag][quad]
    #pragma unroll
    for (int h = 0; h < 2; h++)
        #pragma unroll
        for (int mi = 0; mi < 4; mi++)
            #pragma unroll
            for (int nj = 0; nj < 2; nj++)
                #pragma unroll
                for (int q = 0; q < 4; q++) acc[h][mi][nj][q] = 0.f;
    int dacc[8] = {0,0,0,0,0,0,0,0};

    for (int t = 0; t < NTILES; t++) {
        const uint32_t aBase = offA + (uint32_t)(t & 1) * 16384;
        const uint32_t bBase = offB + (uint32_t)(t % 3) * 16384;

        // 1. convert + STS A(t); degree via dp4a
        #pragma unroll
        for (int k = 0; k < 8; k++) {
            uint32_t t0 = __byte_perm((uint32_t)rA[k].x, (uint32_t)rA[k].y, 0x7430);
            uint32_t t1 = __byte_perm((uint32_t)rA[k].z, (uint32_t)rA[k].w, 0x7430);
            dacc[k] = __dp4a((int)t0, 0x01010101, dacc[k]);
            dacc[k] = __dp4a((int)t1, 0x01010101, dacc[k]);
            sts64(aBase + A_SW0 + (uint32_t)k * 2048, t0 * 0x3F80u, t1 * 0x3F80u);
        }
        // 2. prefetch tile t+1
        if (t + 1 < NTILES) {
            uint32_t bDst = offB + (uint32_t)((t + 1) % 3) * 16384;
            #pragma unroll
            for (int k = 0; k < 4; k++)
                cp_async16(bDst + B_SW0 + k * 4096, bCur + (size_t)k * 32 * N_NODES);
            asm volatile("cp.async.commit_group;" ::: "memory");
            bCur += 64;
            #pragma unroll
            for (int k = 0; k < 8; k++) rA[k] = __ldg(aT + (size_t)k * 16 * (N_NODES / 4));
            aT += 16;
            asm volatile("cp.async.wait_group 1;" ::: "memory");
        } else {
            asm volatile("cp.async.wait_group 0;" ::: "memory");
        }
        __syncthreads();

        // 3. MMA on tile t
        #pragma unroll
        for (int kk = 0; kk < 4; kk++) {
            const uint32_t cb = (uint32_t)(kk * 32);
            uint32_t B0[4], B1[4];
            ldsm4(B0, (bBase + BR0)        ^ (cb + b_cb));   // hi chunk
            ldsm4(B1, (bBase + BR0 + 8192) ^ (cb + b_cb));   // lo chunk
            #pragma unroll
            for (int mi = 0; mi < 4; mi++) {
                uint32_t A0[4];
                ldsm4(A0, (aBase + AR0 + (uint32_t)mi * 2048) ^ (cb + a_ch));
                mma16816(acc[0][mi][0], A0, B0[0], B0[1]);
                mma16816(acc[0][mi][1], A0, B0[2], B0[3]);
                mma16816(acc[1][mi][0], A0, B1[0], B1[1]);
                mma16816(acc[1][mi][1], A0, B1[2], B1[3]);
            }
        }
    }

    // ---- epilogue: combine hi+lo in-register, write partials directly ----
    {
        const int g8 = lane >> 2;
        const int cp = (lane & 3) * 2;
        #pragma unroll
        for (int mi = 0; mi < 4; mi++) {
            int r = iBase + wm * 64 + mi * 16 + g8;
            #pragma unroll
            for (int nj = 0; nj < 2; nj++) {
                int col = wn * 16 + nj * 8 + cp;
                float2 v0, v1;
                v0.x = acc[0][mi][nj][0] + acc[1][mi][nj][0];
                v0.y = acc[0][mi][nj][1] + acc[1][mi][nj][1];
                v1.x = acc[0][mi][nj][2] + acc[1][mi][nj][2];
                v1.y = acc[0][mi][nj][3] + acc[1][mi][nj][3];
                *reinterpret_cast<float2*>(&g_part[js][(size_t)r * OUT_F + col]) = v0;
                *reinterpret_cast<float2*>(&g_part[js][(size_t)(r + 8) * OUT_F + col]) = v1;
            }
        }
    }

    // degree: dacc[k] covers row k*16 + (tid>>4), partials across lanes (tid&15)
    #pragma unroll
    for (int k = 0; k < 8; k++) {
        int v = dacc[k];
        v += __shfl_down_sync(0xffffffffu, v, 8, 16);
        v += __shfl_down_sync(0xffffffffu, v, 4, 16);
        v += __shfl_down_sync(0xffffffffu, v, 2, 16);
        v += __shfl_down_sync(0xffffffffu, v, 1, 16);
        if ((tid & 15) == 0)
            g_deg[js][iBase + k * 16 + (tid >> 4)] = v;
    }
}

// ================ Kernel 3: out = elu(sum(partials)/deg) ================
__global__ void __launch_bounds__(256)
k_finalize(float* __restrict__ out) {
    int g = blockIdx.x * 256 + threadIdx.x;
    int i = g >> 6;
    float s = g_part[0][g] + g_part[1][g] + g_part[2][g];
    float d = (float)(g_deg[0][i] + g_deg[1][i] + g_deg[2][i]);
    float v = s / d;
    out[g] = (v > 0.f) ? v : expm1f(v);
}

// =========================== launch ===========================
#define SMEM_AGG (32768 + 49152 + 1024)

extern "C" void kernel_launch(void* const* d_in, const int* in_sizes, int n_in,
                              void* d_out, int out_size) {
    const int* adj = nullptr;
    const float* x = nullptr;
    const float* W = nullptr;
    for (int k = 0; k < n_in; k++) {
        long long sz = in_sizes[k];
        if (sz == (long long)N_NODES * N_NODES)      adj = (const int*)d_in[k];
        else if (sz == (long long)N_NODES * IN_F)    x = (const float*)d_in[k];
        else if (sz == (long long)IN_F * OUT_F)      W = (const float*)d_in[k];
    }
    float* out = (float*)d_out;

    cudaFuncSetAttribute(k_aggregate, cudaFuncAttributeMaxDynamicSharedMemorySize, SMEM_AGG);

    k_gemm_h<<<N_NODES / 32, 256>>>(x, W);
    k_aggregate<<<dim3(N_NODES / BI, JSPLIT), 256, SMEM_AGG>>>(adj);
    k_finalize<<<(N_NODES * OUT_F) / 256, 256>>>(out);
}